// round 1
// baseline (speedup 1.0000x reference)
#include <cuda_runtime.h>
#include <cuda_bf16.h>
#include <cstdint>

// SSL2d: per-channel sub-pixel bilinear shift with zero padding.
// x: [B=32, C=384, H=56, W=56] fp32, a,b: [C] fp32.
// out[n,c,h,w] = bilinear sample of x[n,c] at (h + a[c], w + b[c]), zero-pad OOB.
//
// Memory-bound: ~308 MB traffic/launch. Strategy: one CTA per (n,c) plane,
// float4-vectorized coalesced writes, predicated coalesced reads.

#define SSL_H 56
#define SSL_W 56
#define SSL_C 384
#define VEC_PER_ROW (SSL_W / 4)            // 14
#define VEC_PER_PLANE (SSL_H * VEC_PER_ROW) // 784

__global__ __launch_bounds__(VEC_PER_PLANE, 2)
void ssl2d_kernel(const float* __restrict__ x,
                  const float* __restrict__ a,
                  const float* __restrict__ b,
                  float* __restrict__ out) {
    const int plane = blockIdx.x;          // n * C + c
    const int c = plane - (plane / SSL_C) * SSL_C;

    const float av = __ldg(a + c);
    const float bv = __ldg(b + c);
    const float iaf = floorf(av);
    const float ibf = floorf(bv);
    const float fa = av - iaf;
    const float fb = bv - ibf;
    const int ia = (int)iaf;
    const int ib = (int)ibf;

    const float w00 = (1.0f - fa) * (1.0f - fb);
    const float w01 = (1.0f - fa) * fb;
    const float w10 = fa * (1.0f - fb);
    const float w11 = fa * fb;

    const float* __restrict__ xp = x + (size_t)plane * (SSL_H * SSL_W);
    float* __restrict__ op       = out + (size_t)plane * (SSL_H * SSL_W);

    const int vid = threadIdx.x;           // 0..783
    const int h = vid / VEC_PER_ROW;
    const int w = (vid - h * VEC_PER_ROW) * 4;

    const int h0 = h + ia;
    const int h1 = h0 + 1;
    const bool vh0 = (h0 >= 0) & (h0 < SSL_H);
    const bool vh1 = (h1 >= 0) & (h1 < SSL_H);
    const int wbase = w + ib;

    const float* row0 = xp + h0 * SSL_W;
    const float* row1 = xp + h1 * SSL_W;

    float r0[5], r1[5];
#pragma unroll
    for (int i = 0; i < 5; i++) {
        const int ws = wbase + i;
        const bool vw = (ws >= 0) & (ws < SSL_W);
        r0[i] = (vh0 & vw) ? __ldg(row0 + ws) : 0.0f;
        r1[i] = (vh1 & vw) ? __ldg(row1 + ws) : 0.0f;
    }

    float4 o;
    o.x = w00 * r0[0] + w01 * r0[1] + w10 * r1[0] + w11 * r1[1];
    o.y = w00 * r0[1] + w01 * r0[2] + w10 * r1[1] + w11 * r1[2];
    o.z = w00 * r0[2] + w01 * r0[3] + w10 * r1[2] + w11 * r1[3];
    o.w = w00 * r0[3] + w01 * r0[4] + w10 * r1[3] + w11 * r1[4];

    *reinterpret_cast<float4*>(op + h * SSL_W + w) = o;
}

extern "C" void kernel_launch(void* const* d_in, const int* in_sizes, int n_in,
                              void* d_out, int out_size) {
    const float* x = (const float*)d_in[0];
    const float* a = (const float*)d_in[1];
    const float* b = (const float*)d_in[2];
    float* out = (float*)d_out;

    const int B = 32;
    const int planes = B * SSL_C;          // 12288
    ssl2d_kernel<<<planes, VEC_PER_PLANE>>>(x, a, b, out);
}